// round 1
// baseline (speedup 1.0000x reference)
#include <cuda_runtime.h>
#include <cuda_bf16.h>
#include <stdint.h>

// Problem constants (fixed shapes)
#define BATCH 8
#define HH 1024
#define WW 1024
#define HW (HH * WW)

#define TILE 32
#define NTHREADS 256

#define HALO_Y 7            // search radius 5 + patch radius 2
#define HALO_RGB 5
#define SY_DIM (TILE + 2 * HALO_Y)      // 46
#define SY_STRIDE 48
#define SRGB_DIM (TILE + 2 * HALO_RGB)  // 42
#define SRGB_STRIDE 44
#define D2_DIM (TILE + 4)               // 36
#define D2_STRIDE 37
#define RS_ROWS (TILE + 4)              // 36

#define N_D2 (D2_DIM * D2_DIM)          // 1296
#define N_RS (RS_ROWS * TILE)           // 1152
#define N_SY (SY_DIM * SY_DIM)          // 2116
#define N_SRGB (SRGB_DIM * SRGB_DIM)    // 1764

// 1 / (H_PARAM + 1e-6)
#define INV_H (1.0f / (1.0f + 1e-6f))

__global__ __launch_bounds__(NTHREADS, 4)
void nlm_kernel(const float* __restrict__ rgb, float* __restrict__ out) {
    __shared__ float sy[SY_DIM * SY_STRIDE];
    __shared__ float sr[SRGB_DIM * SRGB_STRIDE];
    __shared__ float sg[SRGB_DIM * SRGB_STRIDE];
    __shared__ float sb[SRGB_DIM * SRGB_STRIDE];
    __shared__ float sd2[D2_DIM * D2_STRIDE];
    __shared__ float srs[RS_ROWS * TILE];

    const int tid = threadIdx.x;
    const int b   = blockIdx.z;
    const int ty0 = blockIdx.y * TILE;   // tile row origin
    const int tx0 = blockIdx.x * TILE;   // tile col origin

    const float* base = rgb + (size_t)b * 3 * HW;

    // ---- Fill luminance tile (halo 7) ----
    for (int idx = tid; idx < N_SY; idx += NTHREADS) {
        int r = idx / SY_DIM, c = idx - r * SY_DIM;
        int gy = (ty0 + r - HALO_Y) & (HH - 1);
        int gx = (tx0 + c - HALO_Y) & (WW - 1);
        size_t o = (size_t)gy * WW + gx;
        float v = (base[o] + base[o + HW] + base[o + 2 * HW]) * (1.0f / 3.0f);
        sy[r * SY_STRIDE + c] = v;
    }

    // ---- Fill rgb tile (halo 5) ----
    for (int idx = tid; idx < N_SRGB; idx += NTHREADS) {
        int r = idx / SRGB_DIM, c = idx - r * SRGB_DIM;
        int gy = (ty0 + r - HALO_RGB) & (HH - 1);
        int gx = (tx0 + c - HALO_RGB) & (WW - 1);
        size_t o = (size_t)gy * WW + gx;
        int so = r * SRGB_STRIDE + c;
        sr[so] = base[o];
        sg[so] = base[o + HW];
        sb[so] = base[o + 2 * HW];
    }
    __syncthreads();

    // Cache this thread's fixed d2-grid center y values in registers.
    // d2 grid coord (r,c) (r,c in [0,36)) maps to sy local (r+5, c+5).
    float yc[6];
    int d2r[6], d2c[6];
#pragma unroll
    for (int m = 0; m < 6; m++) {
        int idx = tid + NTHREADS * m;
        if (idx < N_D2) {
            int r = idx / D2_DIM, c = idx - r * D2_DIM;
            d2r[m] = r; d2c[m] = c;
            yc[m] = sy[(r + 5) * SY_STRIDE + (c + 5)];
        } else {
            d2r[m] = 0; d2c[m] = 0; yc[m] = 0.0f;
        }
    }

    const int tx  = tid & 31;      // output column within tile
    const int tyb = tid >> 5;      // 0..7 ; rows handled: tyb + 8*m

    float accR[4] = {0.f, 0.f, 0.f, 0.f};
    float accG[4] = {0.f, 0.f, 0.f, 0.f};
    float accB[4] = {0.f, 0.f, 0.f, 0.f};
    float wsum[4] = {0.f, 0.f, 0.f, 0.f};

    for (int dy = -5; dy <= 5; dy++) {
        for (int dx = -5; dx <= 5; dx++) {
            // ---- Stage A: d2[r][c] = (y - y_shifted)^2 over 36x36 region ----
            // image pos = tile + (r-2, c-2); shifted y = y[pos - (dy,dx)]
            // sy local of shifted: (r+5-dy, c+5-dx), always within [0,45]
#pragma unroll
            for (int m = 0; m < 6; m++) {
                int idx = tid + NTHREADS * m;
                if (idx < N_D2) {
                    int r = d2r[m], c = d2c[m];
                    float ysh = sy[(r + 5 - dy) * SY_STRIDE + (c + 5 - dx)];
                    float d = yc[m] - ysh;
                    sd2[r * D2_STRIDE + c] = d * d;
                }
            }
            __syncthreads();

            // ---- Stage B: horizontal 5-sum. rs[k][j] = sum_{u=0..4} d2[k][j+u]
#pragma unroll
            for (int m = 0; m < 5; m++) {
                int idx = tid + NTHREADS * m;
                if (idx < N_RS) {
                    int k = idx >> 5, j = idx & 31;
                    const float* p = &sd2[k * D2_STRIDE + j];
                    srs[k * TILE + j] = ((p[0] + p[1]) + (p[2] + p[3])) + p[4];
                }
            }
            __syncthreads();

            // ---- Stage C: vertical 5-sum + weight + accumulate ----
#pragma unroll
            for (int m = 0; m < 4; m++) {
                int i = tyb + 8 * m;
                const float* q = &srs[i * TILE + tx];
                float S = ((q[0 * TILE] + q[1 * TILE]) +
                           (q[2 * TILE] + q[3 * TILE])) + q[4 * TILE];
                float w = __expf(-sqrtf(S) * INV_H);
                int so = (i - dy + HALO_RGB) * SRGB_STRIDE + (tx - dx + HALO_RGB);
                accR[m] = fmaf(sr[so], w, accR[m]);
                accG[m] = fmaf(sg[so], w, accG[m]);
                accB[m] = fmaf(sb[so], w, accB[m]);
                wsum[m] += w;
            }
            // No barrier needed between C and next A (disjoint arrays);
            // the sync after next A orders C's srs reads before B's writes.
        }
    }

    // ---- Write out: out = acc / wsum ----
    float* outb = out + (size_t)b * 3 * HW;
#pragma unroll
    for (int m = 0; m < 4; m++) {
        int i = tyb + 8 * m;
        size_t o = (size_t)(ty0 + i) * WW + (tx0 + tx);
        float inv = 1.0f / wsum[m];
        outb[o]          = accR[m] * inv;
        outb[o + HW]     = accG[m] * inv;
        outb[o + 2 * HW] = accB[m] * inv;
    }
}

extern "C" void kernel_launch(void* const* d_in, const int* in_sizes, int n_in,
                              void* d_out, int out_size) {
    const float* rgb = (const float*)d_in[0];
    float* out = (float*)d_out;
    dim3 grid(WW / TILE, HH / TILE, BATCH);
    nlm_kernel<<<grid, NTHREADS>>>(rgb, out);
}

// round 2
// speedup vs baseline: 1.6068x; 1.6068x over previous
#include <cuda_runtime.h>
#include <cuda_bf16.h>
#include <stdint.h>

// Problem constants (fixed shapes)
#define BATCH 8
#define HH 1024
#define WW 1024
#define HW (HH * WW)

#define TILE 32
#define NTHREADS 256

#define HALO_Y 7            // search radius 5 + patch radius 2
#define HALO_RGB 5
#define SY_DIM 46           // 32 + 2*7
#define SY_STRIDE 48
#define SRGB_DIM 42         // 32 + 2*5
#define SRGB_STRIDE 45      // odd -> conflict-free for stage-C pattern
#define CS_COLS 36          // columns j in [-2, 34)
#define CS_STRIDE 37        // odd -> conflict-free for stage-C pattern

#define N_SY (SY_DIM * SY_DIM)
#define N_SRGB (SRGB_DIM * SRGB_DIM)
#define N_CS_TASKS 252      // 7 vertical runs x 36 columns

#define INV_H (1.0f / (1.0f + 1e-6f))

// Vertical run start rows: 7 runs of length 5 covering rows 0..31 (overlaps
// at 24..28 and 27..31 write identical values -> benign).
__device__ __constant__ int c_i0[7] = {0, 5, 10, 15, 20, 24, 27};

__global__ __launch_bounds__(NTHREADS, 3)
void nlm_kernel(const float* __restrict__ rgb, float* __restrict__ out) {
    __shared__ float sy[SY_DIM * SY_STRIDE];
    __shared__ float sr[SRGB_DIM * SRGB_STRIDE];
    __shared__ float sg[SRGB_DIM * SRGB_STRIDE];
    __shared__ float sb[SRGB_DIM * SRGB_STRIDE];
    __shared__ float cs[2][TILE * CS_STRIDE];   // double-buffered column sums

    const int tid = threadIdx.x;
    const int b   = blockIdx.z;
    const int ty0 = blockIdx.y * TILE;
    const int tx0 = blockIdx.x * TILE;

    const float* base = rgb + (size_t)b * 3 * HW;

    // ---- Fill luminance tile (halo 7) ----
    for (int idx = tid; idx < N_SY; idx += NTHREADS) {
        int r = idx / SY_DIM, c = idx - r * SY_DIM;
        int gy = (ty0 + r - HALO_Y) & (HH - 1);
        int gx = (tx0 + c - HALO_Y) & (WW - 1);
        size_t o = (size_t)gy * WW + gx;
        sy[r * SY_STRIDE + c] =
            (base[o] + base[o + HW] + base[o + 2 * HW]) * (1.0f / 3.0f);
    }

    // ---- Fill rgb tile (halo 5) ----
    for (int idx = tid; idx < N_SRGB; idx += NTHREADS) {
        int r = idx / SRGB_DIM, c = idx - r * SRGB_DIM;
        int gy = (ty0 + r - HALO_RGB) & (HH - 1);
        int gx = (tx0 + c - HALO_RGB) & (WW - 1);
        size_t o = (size_t)gy * WW + gx;
        int so = r * SRGB_STRIDE + c;
        sr[so] = base[o];
        sg[so] = base[o + HW];
        sb[so] = base[o + 2 * HW];
    }
    __syncthreads();

    // ---- Stage-AB task: vertical run of 5 cs outputs in one column ----
    // task (col-major over runs): col = task % 36, run = task / 36
    const int tk   = (tid < N_CS_TASKS) ? tid : 0;
    const int col  = tk % CS_COLS;           // cs column index (image col = col-2)
    const int run  = tk / CS_COLS;
    const int i0   = c_i0[run];

    // Center-y values for this thread's 9 d2 rows — FIXED across all shifts.
    float yc[9];
#pragma unroll
    for (int u = 0; u < 9; u++)
        yc[u] = sy[(i0 + 5 + u) * SY_STRIDE + (col + 5)];

    // ---- Stage-C task: 4 consecutive output columns in one row ----
    const int ci  = tid >> 3;        // output row 0..31
    const int cj0 = (tid & 7) * 4;   // output col start

    float accR[4] = {0.f, 0.f, 0.f, 0.f};
    float accG[4] = {0.f, 0.f, 0.f, 0.f};
    float accB[4] = {0.f, 0.f, 0.f, 0.f};
    float wsum[4] = {0.f, 0.f, 0.f, 0.f};

    int buf = 0;
    for (int dy = -5; dy <= 5; dy++) {
        for (int dx = -5; dx <= 5; dx++) {
            // ---- Stage AB: fused d2 + vertical 5-sum -> cs[buf] ----
            if (tid < N_CS_TASKS) {
                const float* shp =
                    &sy[(i0 + 5 - dy) * SY_STRIDE + (col + 5 - dx)];
                float d[9];
#pragma unroll
                for (int u = 0; u < 9; u++) {
                    float dd = yc[u] - shp[u * SY_STRIDE];
                    d[u] = dd * dd;
                }
                float s = ((d[0] + d[1]) + (d[2] + d[3])) + d[4];
                float* cp = &cs[buf][i0 * CS_STRIDE + col];
                cp[0 * CS_STRIDE] = s;
#pragma unroll
                for (int v = 1; v < 5; v++) {
                    s += d[v + 4] - d[v - 1];
                    cp[v * CS_STRIDE] = s;
                }
            }
            __syncthreads();

            // ---- Stage C: horizontal 5-sum (sliding) + weight + accumulate ----
            float q[8];
            const float* cq = &cs[buf][ci * CS_STRIDE + cj0];
#pragma unroll
            for (int m = 0; m < 8; m++) q[m] = cq[m];

            const int sobase =
                (ci - dy + HALO_RGB) * SRGB_STRIDE + (cj0 - dx + HALO_RGB);
#pragma unroll
            for (int m = 0; m < 4; m++) {
                float S = ((q[m] + q[m + 1]) + (q[m + 2] + q[m + 3])) + q[m + 4];
                float w = __expf(-sqrtf(S) * INV_H);
                int so = sobase + m;
                accR[m] = fmaf(sr[so], w, accR[m]);
                accG[m] = fmaf(sg[so], w, accG[m]);
                accB[m] = fmaf(sb[so], w, accB[m]);
                wsum[m] += w;
            }
            buf ^= 1;
            // No second barrier: cs is double-buffered; the next iteration's
            // writes target the other buffer, and the barrier above orders
            // this iteration's reads against writes two iterations out.
        }
    }

    // ---- Write out: out = acc / wsum, float4 per channel ----
    float* outb = out + (size_t)b * 3 * HW;
    size_t o = (size_t)(ty0 + ci) * WW + (tx0 + cj0);
    float inv0 = 1.0f / wsum[0], inv1 = 1.0f / wsum[1];
    float inv2 = 1.0f / wsum[2], inv3 = 1.0f / wsum[3];
    *(float4*)&outb[o] =
        make_float4(accR[0] * inv0, accR[1] * inv1, accR[2] * inv2, accR[3] * inv3);
    *(float4*)&outb[o + HW] =
        make_float4(accG[0] * inv0, accG[1] * inv1, accG[2] * inv2, accG[3] * inv3);
    *(float4*)&outb[o + 2 * HW] =
        make_float4(accB[0] * inv0, accB[1] * inv1, accB[2] * inv2, accB[3] * inv3);
}

extern "C" void kernel_launch(void* const* d_in, const int* in_sizes, int n_in,
                              void* d_out, int out_size) {
    const float* rgb = (const float*)d_in[0];
    float* out = (float*)d_out;
    dim3 grid(WW / TILE, HH / TILE, BATCH);
    nlm_kernel<<<grid, NTHREADS>>>(rgb, out);
}

// round 3
// speedup vs baseline: 1.7734x; 1.1037x over previous
#include <cuda_runtime.h>
#include <cuda_bf16.h>
#include <stdint.h>

// Problem constants (fixed shapes)
#define BATCH 8
#define HH 1024
#define WW 1024
#define HW (HH * WW)

#define TILE 32
#define NTHREADS 256

#define HALO_Y 7            // search radius 5 + patch radius 2
#define HALO_RGB 5
#define SY_DIM 46           // 32 + 2*7
#define SY_STRIDE 48
#define SRGB_DIM 42         // 32 + 2*5
#define SRGB_STRIDE 45      // odd -> conflict-free for stage-C pattern
#define CS_COLS 36          // columns j in [-2, 34)
#define CS_STRIDE 37        // odd -> conflict-free for stage-C pattern

#define N_SY (SY_DIM * SY_DIM)
#define N_SRGB (SRGB_DIM * SRGB_DIM)
#define N_CS_TASKS 252      // 7 vertical runs x 36 columns

#define INV_H (1.0f / (1.0f + 1e-6f))

// Vertical run start rows: 7 runs of length 5 covering rows 0..31 (overlaps
// at 24..28 and 27..31 write identical values -> benign).
__device__ __constant__ int c_i0[7] = {0, 5, 10, 15, 20, 24, 27};

__global__ __launch_bounds__(NTHREADS, 3)
void nlm_kernel(const float* __restrict__ rgb, float* __restrict__ out) {
    __shared__ float sy[SY_DIM * SY_STRIDE];
    __shared__ float sr[SRGB_DIM * SRGB_STRIDE];
    __shared__ float sg[SRGB_DIM * SRGB_STRIDE];
    __shared__ float sb[SRGB_DIM * SRGB_STRIDE];
    __shared__ float cs[2][TILE * CS_STRIDE];   // double-buffered column sums

    const int tid = threadIdx.x;
    const int b   = blockIdx.z;
    const int ty0 = blockIdx.y * TILE;
    const int tx0 = blockIdx.x * TILE;

    const float* base = rgb + (size_t)b * 3 * HW;

    // ---- Fill luminance tile (halo 7) ----
    for (int idx = tid; idx < N_SY; idx += NTHREADS) {
        int r = idx / SY_DIM, c = idx - r * SY_DIM;
        int gy = (ty0 + r - HALO_Y) & (HH - 1);
        int gx = (tx0 + c - HALO_Y) & (WW - 1);
        size_t o = (size_t)gy * WW + gx;
        sy[r * SY_STRIDE + c] =
            (base[o] + base[o + HW] + base[o + 2 * HW]) * (1.0f / 3.0f);
    }

    // ---- Fill rgb tile (halo 5) ----
    for (int idx = tid; idx < N_SRGB; idx += NTHREADS) {
        int r = idx / SRGB_DIM, c = idx - r * SRGB_DIM;
        int gy = (ty0 + r - HALO_RGB) & (HH - 1);
        int gx = (tx0 + c - HALO_RGB) & (WW - 1);
        size_t o = (size_t)gy * WW + gx;
        int so = r * SRGB_STRIDE + c;
        sr[so] = base[o];
        sg[so] = base[o + HW];
        sb[so] = base[o + 2 * HW];
    }
    __syncthreads();

    // ---- Stage-AB task: vertical run of 5 cs outputs in one column ----
    const int tk   = (tid < N_CS_TASKS) ? tid : 0;
    const int col  = tk % CS_COLS;           // cs column index (image col = col-2)
    const int run  = tk / CS_COLS;
    const int i0   = c_i0[run];

    // Center-y values for this thread's 9 d2 rows — FIXED across all shifts.
    float yc[9];
#pragma unroll
    for (int u = 0; u < 9; u++)
        yc[u] = sy[(i0 + 5 + u) * SY_STRIDE + (col + 5)];

    // ---- Stage-C task: 4 consecutive output columns in one row ----
    const int ci  = tid >> 3;        // output row 0..31
    const int cj0 = (tid & 7) * 4;   // output col start

    float accR[4] = {0.f, 0.f, 0.f, 0.f};
    float accG[4] = {0.f, 0.f, 0.f, 0.f};
    float accB[4] = {0.f, 0.f, 0.f, 0.f};
    float wsum[4] = {0.f, 0.f, 0.f, 0.f};

    int buf = 0;
#pragma unroll 1
    for (int dx = -5; dx <= 5; dx++) {
        // Shifted-y column pointer for this dx (fixed within the dy loop).
        const float* ycol = &sy[col + 5 - dx];

        // Preload the 9-row shifted-y window for dy = -5:
        // rows (i0 + 5 - dy) + u = i0 + 10 + u
        float ysh[9];
#pragma unroll
        for (int u = 0; u < 9; u++)
            ysh[u] = ycol[(i0 + 10 + u) * SY_STRIDE];

#pragma unroll
        for (int dy = -5; dy <= 5; dy++) {
            // ---- Stage AB: fused d2 + vertical 5-sum -> cs[buf] ----
            if (tid < N_CS_TASKS) {
                float d[9];
#pragma unroll
                for (int u = 0; u < 9; u++) {
                    float dd = yc[u] - ysh[u];
                    d[u] = dd * dd;
                }
                float s = ((d[0] + d[1]) + (d[2] + d[3])) + d[4];
                float* cp = &cs[buf][i0 * CS_STRIDE + col];
                cp[0 * CS_STRIDE] = s;
#pragma unroll
                for (int v = 1; v < 5; v++) {
                    s += d[v + 4] - d[v - 1];
                    cp[v * CS_STRIDE] = s;
                }
            }
            __syncthreads();

            // ---- Stage C: horizontal 5-sum (sliding) + weight + accumulate ----
            float q[8];
            const float* cq = &cs[buf][ci * CS_STRIDE + cj0];
#pragma unroll
            for (int m = 0; m < 8; m++) q[m] = cq[m];

            const int sobase =
                (ci - dy + HALO_RGB) * SRGB_STRIDE + (cj0 - dx + HALO_RGB);
#pragma unroll
            for (int m = 0; m < 4; m++) {
                float S = ((q[m] + q[m + 1]) + (q[m + 2] + q[m + 3])) + q[m + 4];
                float w = __expf(-sqrtf(S) * INV_H);
                int so = sobase + m;
                accR[m] = fmaf(sr[so], w, accR[m]);
                accG[m] = fmaf(sg[so], w, accG[m]);
                accB[m] = fmaf(sb[so], w, accB[m]);
                wsum[m] += w;
            }
            buf ^= 1;
            // No second barrier: cs is double-buffered; the barrier above
            // orders this iteration's reads against writes two iterations out.

            // ---- Slide the shifted-y window down one row (for dy+1) ----
            if (dy < 5) {
#pragma unroll
                for (int u = 8; u >= 1; u--) ysh[u] = ysh[u - 1];
                ysh[0] = ycol[(i0 + 4 - dy) * SY_STRIDE];
            }
        }
    }

    // ---- Write out: out = acc / wsum, float4 per channel ----
    float* outb = out + (size_t)b * 3 * HW;
    size_t o = (size_t)(ty0 + ci) * WW + (tx0 + cj0);
    float inv0 = 1.0f / wsum[0], inv1 = 1.0f / wsum[1];
    float inv2 = 1.0f / wsum[2], inv3 = 1.0f / wsum[3];
    *(float4*)&outb[o] =
        make_float4(accR[0] * inv0, accR[1] * inv1, accR[2] * inv2, accR[3] * inv3);
    *(float4*)&outb[o + HW] =
        make_float4(accG[0] * inv0, accG[1] * inv1, accG[2] * inv2, accG[3] * inv3);
    *(float4*)&outb[o + 2 * HW] =
        make_float4(accB[0] * inv0, accB[1] * inv1, accB[2] * inv2, accB[3] * inv3);
}

extern "C" void kernel_launch(void* const* d_in, const int* in_sizes, int n_in,
                              void* d_out, int out_size) {
    const float* rgb = (const float*)d_in[0];
    float* out = (float*)d_out;
    dim3 grid(WW / TILE, HH / TILE, BATCH);
    nlm_kernel<<<grid, NTHREADS>>>(rgb, out);
}

// round 4
// speedup vs baseline: 2.1250x; 1.1982x over previous
#include <cuda_runtime.h>
#include <cuda_bf16.h>
#include <stdint.h>

// Problem constants (fixed shapes)
#define BATCH 8
#define HH 1024
#define WW 1024
#define HW (HH * WW)

#define TILE 32
#define NTHREADS 256

#define HALO_Y 7            // search radius 5 + patch radius 2
#define HALO_RGB 5
#define SY_DIM 46           // 32 + 2*7
#define SY_STRIDE 48
#define SRGB_DIM 42         // 32 + 2*5
#define SRGB_STRIDE 45      // odd -> conflict-free for stage-C rgb pattern
#define CS_COLS 36          // columns j in [-2, 34)
#define CS_STRIDE 40        // multiple of 4 -> LDS.128-able in stage C

#define N_SY (SY_DIM * SY_DIM)
#define N_SRGB (SRGB_DIM * SRGB_DIM)
#define N_CS_TASKS 252      // 7 vertical runs x 36 columns

#define INV_H (1.0f / (1.0f + 1e-6f))

__device__ __forceinline__ float rsqrt_approx(float x) {
    float r;
    asm("rsqrt.approx.f32 %0, %1;" : "=f"(r) : "f"(x));
    return r;
}

// Vertical run start rows: 7 runs of length 5 covering rows 0..31 (overlaps
// write identical values -> benign).
__device__ __constant__ int c_i0[7] = {0, 5, 10, 15, 20, 24, 27};

__global__ __launch_bounds__(NTHREADS, 3)
void nlm_kernel(const float* __restrict__ rgb, float* __restrict__ out) {
    __shared__ float sy[SY_DIM * SY_STRIDE];
    __shared__ float sr[SRGB_DIM * SRGB_STRIDE];
    __shared__ float sg[SRGB_DIM * SRGB_STRIDE];
    __shared__ float sb[SRGB_DIM * SRGB_STRIDE];
    __shared__ __align__(16) float cs[2][TILE * CS_STRIDE];  // double-buffered

    const int tid = threadIdx.x;
    const int b   = blockIdx.z;
    const int ty0 = blockIdx.y * TILE;
    const int tx0 = blockIdx.x * TILE;

    const float* base = rgb + (size_t)b * 3 * HW;

    // ---- Fill luminance tile (halo 7) ----
    for (int idx = tid; idx < N_SY; idx += NTHREADS) {
        int r = idx / SY_DIM, c = idx - r * SY_DIM;
        int gy = (ty0 + r - HALO_Y) & (HH - 1);
        int gx = (tx0 + c - HALO_Y) & (WW - 1);
        size_t o = (size_t)gy * WW + gx;
        sy[r * SY_STRIDE + c] =
            (base[o] + base[o + HW] + base[o + 2 * HW]) * (1.0f / 3.0f);
    }

    // ---- Fill rgb tile (halo 5) ----
    for (int idx = tid; idx < N_SRGB; idx += NTHREADS) {
        int r = idx / SRGB_DIM, c = idx - r * SRGB_DIM;
        int gy = (ty0 + r - HALO_RGB) & (HH - 1);
        int gx = (tx0 + c - HALO_RGB) & (WW - 1);
        size_t o = (size_t)gy * WW + gx;
        int so = r * SRGB_STRIDE + c;
        sr[so] = base[o];
        sg[so] = base[o + HW];
        sb[so] = base[o + 2 * HW];
    }
    __syncthreads();

    // ---- Stage-AB task: vertical run of 5 cs outputs in one column ----
    const int tk   = (tid < N_CS_TASKS) ? tid : 0;
    const int col  = tk % CS_COLS;           // cs column (image col = col-2)
    const int run  = tk / CS_COLS;
    const int i0   = c_i0[run];

    // Center-y values for this thread's 9 d2 rows — FIXED across all shifts.
    float yc[9];
#pragma unroll
    for (int u = 0; u < 9; u++)
        yc[u] = sy[(i0 + 5 + u) * SY_STRIDE + (col + 5)];

    // ---- Stage-C task: 4 consecutive output columns in one row ----
    const int ci  = tid >> 3;        // output row 0..31
    const int cj0 = (tid & 7) * 4;   // output col start

    float accR[4] = {0.f, 0.f, 0.f, 0.f};
    float accG[4] = {0.f, 0.f, 0.f, 0.f};
    float accB[4] = {0.f, 0.f, 0.f, 0.f};
    float wsum[4] = {0.f, 0.f, 0.f, 0.f};

    int buf = 0;
#pragma unroll 1
    for (int dx = -5; dx <= 5; dx++) {
        // Shifted-y column pointer for this dx (fixed within the dy loop).
        const float* ycol = &sy[col + 5 - dx];

        // Preload the 9-row shifted-y window for dy = -5:
        float ysh[9];
#pragma unroll
        for (int u = 0; u < 9; u++)
            ysh[u] = ycol[(i0 + 10 + u) * SY_STRIDE];

#pragma unroll
        for (int dy = -5; dy <= 5; dy++) {
            // ---- Stage AB: fused d2 + vertical 5-sum -> cs[buf] ----
            if (tid < N_CS_TASKS) {
                float d[9];
#pragma unroll
                for (int u = 0; u < 9; u++) {
                    float dd = yc[u] - ysh[u];
                    d[u] = dd * dd;
                }
                float s = ((d[0] + d[1]) + (d[2] + d[3])) + d[4];
                float* cp = &cs[buf][i0 * CS_STRIDE + col];
                cp[0 * CS_STRIDE] = s;
#pragma unroll
                for (int v = 1; v < 5; v++) {
                    s += d[v + 4] - d[v - 1];
                    cp[v * CS_STRIDE] = s;
                }
            }
            __syncthreads();

            // ---- Stage C: horizontal sliding 5-sum + weight + accumulate ----
            const float4* cq =
                (const float4*)&cs[buf][ci * CS_STRIDE + cj0];
            float4 v0 = cq[0];
            float4 v1 = cq[1];

            float S0 = ((v0.x + v0.y) + (v0.z + v0.w)) + v1.x;
            float S1 = S0 + (v1.y - v0.x);
            float S2 = S1 + (v1.z - v0.y);
            float S3 = S2 + (v1.w - v0.z);

            const int sobase =
                (ci - dy + HALO_RGB) * SRGB_STRIDE + (cj0 - dx + HALO_RGB);
            float S[4] = {S0, S1, S2, S3};
#pragma unroll
            for (int m = 0; m < 4; m++) {
                float t  = fmaxf(S[m], 1e-20f);
                float sq = S[m] * rsqrt_approx(t);     // ~= sqrt(S)
                float w  = __expf(-sq * INV_H);
                int so = sobase + m;
                accR[m] = fmaf(sr[so], w, accR[m]);
                accG[m] = fmaf(sg[so], w, accG[m]);
                accB[m] = fmaf(sb[so], w, accB[m]);
                wsum[m] += w;
            }
            buf ^= 1;
            // cs is double-buffered; the barrier above orders this
            // iteration's reads against writes two iterations out.

            // ---- Slide the shifted-y window down one row (for dy+1) ----
            if (dy < 5) {
#pragma unroll
                for (int u = 8; u >= 1; u--) ysh[u] = ysh[u - 1];
                ysh[0] = ycol[(i0 + 4 - dy) * SY_STRIDE];
            }
        }
    }

    // ---- Write out: out = acc / wsum, float4 per channel ----
    float* outb = out + (size_t)b * 3 * HW;
    size_t o = (size_t)(ty0 + ci) * WW + (tx0 + cj0);
    float inv0 = 1.0f / wsum[0], inv1 = 1.0f / wsum[1];
    float inv2 = 1.0f / wsum[2], inv3 = 1.0f / wsum[3];
    *(float4*)&outb[o] =
        make_float4(accR[0] * inv0, accR[1] * inv1, accR[2] * inv2, accR[3] * inv3);
    *(float4*)&outb[o + HW] =
        make_float4(accG[0] * inv0, accG[1] * inv1, accG[2] * inv2, accG[3] * inv3);
    *(float4*)&outb[o + 2 * HW] =
        make_float4(accB[0] * inv0, accB[1] * inv1, accB[2] * inv2, accB[3] * inv3);
}

extern "C" void kernel_launch(void* const* d_in, const int* in_sizes, int n_in,
                              void* d_out, int out_size) {
    const float* rgb = (const float*)d_in[0];
    float* out = (float*)d_out;
    dim3 grid(WW / TILE, HH / TILE, BATCH);
    nlm_kernel<<<grid, NTHREADS>>>(rgb, out);
}